// round 13
// baseline (speedup 1.0000x reference)
#include <cuda_runtime.h>
#include <cuda_bf16.h>
#include <cstdint>

#define NB 8
#define LQ 1024
#define LK 8192
#define DIMD 256
#define DC 128
#define FEPS 1e-6f
#define ONE_MEPS (1.0f - 1e-6f)
#define AQ0 (1.0f - ONE_MEPS)

// -------------------- device scratch (no allocs allowed) --------------------
__device__ __nv_bfloat16 g_G[DC * DC];                 // W^T W, bf16, row-major
__device__ __nv_bfloat16 g_qp[NB * LQ * DC];           // q' = q @ W_up, bf16
__device__ float2 g_qinfo[NB * LQ];                    // (q_sq, 1-min(q_sq,1-eps))
__device__ __nv_bfloat16 g_kc[(size_t)NB * LK * DC];   // dequantized k_c, bf16
__device__ float2 g_kinfo[NB * LK];                    // (k_sq, 1-min(k_sq,1-eps))

// -------------------- helpers --------------------
static __device__ __forceinline__ uint32_t smem_u32(const void* p) {
    uint32_t a;
    asm("{ .reg .u64 t; cvta.to.shared.u64 t, %1; cvt.u32.u64 %0, t; }" : "=r"(a) : "l"(p));
    return a;
}

#define LDSM4(r0, r1, r2, r3, a) \
    asm volatile("ldmatrix.sync.aligned.m8n8.x4.shared.b16 {%0,%1,%2,%3}, [%4];" \
                 : "=r"(r0), "=r"(r1), "=r"(r2), "=r"(r3) : "r"(a))

#define LDSM4T(r0, r1, r2, r3, a) \
    asm volatile("ldmatrix.sync.aligned.m8n8.x4.trans.shared.b16 {%0,%1,%2,%3}, [%4];" \
                 : "=r"(r0), "=r"(r1), "=r"(r2), "=r"(r3) : "r"(a))

#define MMA16816(c, a0, a1, a2, a3, b0, b1) \
    asm volatile("mma.sync.aligned.m16n8k16.row.col.f32.bf16.bf16.f32 " \
                 "{%0,%1,%2,%3},{%4,%5,%6,%7},{%8,%9},{%0,%1,%2,%3};" \
                 : "+f"((c)[0]), "+f"((c)[1]), "+f"((c)[2]), "+f"((c)[3]) \
                 : "r"(a0), "r"(a1), "r"(a2), "r"(a3), "r"(b0), "r"(b1))

static __device__ __forceinline__ uint32_t pack_bf16(float a, float b) {
    __nv_bfloat162 h = __floats2bfloat162_rn(a, b);
    return *reinterpret_cast<uint32_t*>(&h);
}

// -------------------- SMEM layouts --------------------
#define TSTRIDE 272
#define OFF_A 0                       // 34816 B
#define OFF_B 34816                   // 34816 B
#define OFF_INFO 69632                // 1024 B
#define SMEM_DYN 70656
// prep_q: A = q tile 64 rows x 256 bf16, stride 528B; W native 256 rows x 128 bf16, stride 272B.
#define QSTRIDE 528
#define QOFF_A 0                      // 64*528 = 33792
#define QOFF_W 33792                  // 256*272 = 69632 -> ends 103424
#define QOFF_SQ 103424                // float[64]
#define SMEM_Q 103936

// ---- warp-tile GEMM: 32(M) x 64(N) per warp, K = 128, both operands k-major ----
static __device__ __forceinline__ void gemm_wt(uint32_t aBase, uint32_t bBase,
                                               int m0, int n0, int lane, float* acc) {
    uint32_t aAddr0 = aBase + (uint32_t)(m0 + (lane & 15)) * TSTRIDE + (uint32_t)((lane >> 4) << 4);
    uint32_t aAddr1 = aAddr0 + 16 * TSTRIDE;
    uint32_t bAddr = bBase + (uint32_t)(n0 + (lane & 7) + ((lane >> 4) << 3)) * TSTRIDE +
                     (uint32_t)(((lane >> 3) & 1) << 4);
#pragma unroll
    for (int kk = 0; kk < 8; kk++) {
        uint32_t a0, a1, a2, a3, c0, c1, c2, c3;
        LDSM4(a0, a1, a2, a3, aAddr0 + kk * 32);
        LDSM4(c0, c1, c2, c3, aAddr1 + kk * 32);
#pragma unroll
        for (int j = 0; j < 4; j++) {
            uint32_t b0, b1, b2, b3;
            LDSM4(b0, b1, b2, b3, bAddr + j * (16 * TSTRIDE) + kk * 32);
            MMA16816(acc + (2 * j) * 8 + 0, a0, a1, a2, a3, b0, b1);
            MMA16816(acc + (2 * j) * 8 + 4, c0, c1, c2, c3, b0, b1);
            MMA16816(acc + (2 * j + 1) * 8 + 0, a0, a1, a2, a3, b2, b3);
            MMA16816(acc + (2 * j + 1) * 8 + 4, c0, c1, c2, c3, b2, b3);
        }
    }
}

// ---- prep_q GEMM: warp tile 32(M) x 32(N), K=256; B = W native row-major via ldmatrix.trans ----
static __device__ __forceinline__ void gemm_qw32(uint32_t aBase, uint32_t wBase,
                                                 int m0, int n0, int lane, float* acc) {
    uint32_t aAddr0 = aBase + (uint32_t)(m0 + (lane & 15)) * QSTRIDE + (uint32_t)((lane >> 4) << 4);
    uint32_t aAddr1 = aAddr0 + 16 * QSTRIDE;
    uint32_t bAddr = wBase + (uint32_t)(lane & 15) * TSTRIDE + (uint32_t)((lane >> 4) << 4) +
                     (uint32_t)(n0 * 2);
#pragma unroll
    for (int kk = 0; kk < 16; kk++) {
        uint32_t a0, a1, a2, a3, c0, c1, c2, c3;
        LDSM4(a0, a1, a2, a3, aAddr0 + kk * 32);
        LDSM4(c0, c1, c2, c3, aAddr1 + kk * 32);
        uint32_t brow = bAddr + (uint32_t)(kk * 16) * TSTRIDE;
#pragma unroll
        for (int j = 0; j < 2; j++) {
            uint32_t b0, b1, b2, b3;
            LDSM4T(b0, b1, b2, b3, brow + j * 32);
            MMA16816(acc + (2 * j) * 8 + 0, a0, a1, a2, a3, b0, b1);
            MMA16816(acc + (2 * j) * 8 + 4, c0, c1, c2, c3, b0, b1);
            MMA16816(acc + (2 * j + 1) * 8 + 0, a0, a1, a2, a3, b2, b3);
            MMA16816(acc + (2 * j + 1) * 8 + 4, c0, c1, c2, c3, b2, b3);
        }
    }
}

// ---- legacy 8x1 warp tiling (kept for prep_k) ----
static __device__ __forceinline__ void gemm128(uint32_t aBase, uint32_t bBase,
                                               int wid, int lane, float* acc) {
    uint32_t aAddr = aBase + (uint32_t)(wid * 16 + (lane & 15)) * TSTRIDE +
                     (uint32_t)((lane >> 4) << 4);
    uint32_t bAddr = bBase + (uint32_t)((lane & 7) + ((lane >> 4) << 3)) * TSTRIDE +
                     (uint32_t)(((lane >> 3) & 1) << 4);
#pragma unroll
    for (int kk = 0; kk < 8; kk++) {
        uint32_t a0, a1, a2, a3;
        LDSM4(a0, a1, a2, a3, aAddr + kk * 32);
#pragma unroll
        for (int nt2 = 0; nt2 < 8; nt2++) {
            uint32_t b0, b1, b2, b3;
            LDSM4(b0, b1, b2, b3, bAddr + nt2 * (16 * TSTRIDE) + kk * 32);
            MMA16816(acc + nt2 * 8, a0, a1, a2, a3, b0, b1);
            MMA16816(acc + nt2 * 8 + 4, a0, a1, a2, a3, b2, b3);
        }
    }
}

// general path (rare): full clamp math incl. per-pair division
static __device__ __forceinline__ float hdist(float qk, float qs, float aq, float2 ki) {
    float diff = fmaxf(fmaf(qk, -2.f, qs + ki.x), 0.f);
    float den = fmaf(aq, ki.y, FEPS);
    float x = __fdividef(diff + diff, den) + 1.f;
    float arg;
    if (x > 100.f) arg = x + x;
    else arg = x + sqrtf(fmaxf(fmaf(x, x, -1.f), 0.f));
    return __logf(arg);
}

// fast path: den == den0 constant; dist = ln(4*diff/den0), exact fallback for small diff
static __device__ __forceinline__ float fast_dist(float diff, float c4, float rden0) {
    float v = diff * c4;                      // 4*diff/den0
    if (v > 1e4f) return __logf(v);
    float x = fmaf(diff + diff, rden0, 1.f);  // 1 + 2*diff/den0
    return __logf(x + sqrtf(fmaxf(fmaf(x, x, -1.f), 0.f)));
}

// ==================== kernel 1: G = W^T W (bf16) ====================
__global__ void prep_G_kernel(const float* __restrict__ W) {
    int idx = blockIdx.x * 256 + threadIdx.x;  // 16384 entries
    int c = idx >> 7, c2 = idx & 127;
    float s = 0.f;
#pragma unroll 4
    for (int d = 0; d < DIMD; d++) s = fmaf(W[d * DC + c], W[d * DC + c2], s);
    g_G[idx] = __float2bfloat16(s);
}

// ==================== kernel 2: q' = q @ W_up (tensor), q_sq (fp32 exact) ====================
__global__ void __launch_bounds__(256) prep_q_kernel(const float* __restrict__ q,
                                                     const float* __restrict__ W) {
    extern __shared__ char sm[];
    const int t = threadIdx.x, wid = t >> 5, lane = t & 31;
    const size_t q0 = (size_t)blockIdx.x * 64;
    float* qsq = (float*)(sm + QOFF_SQ);

    if (t < 64) qsq[t] = 0.f;
    __syncthreads();

    // A load: q tile 64 x 256 fp32 -> bf16 (stride 528), accumulate q_sq (fp32 exact).
#pragma unroll 4
    for (int j = 0; j < 16; j++) {
        int ci = t + j * 256;               // float4-chunk index: 64 per row
        int row = ci >> 6, c4 = ci & 63;
        float4 v = *(const float4*)(q + (q0 + row) * DIMD + c4 * 4);
        uint2 pk;
        pk.x = pack_bf16(v.x, v.y);
        pk.y = pack_bf16(v.z, v.w);
        *(uint2*)(sm + QOFF_A + row * QSTRIDE + c4 * 8) = pk;
        float red = v.x * v.x + v.y * v.y + v.z * v.z + v.w * v.w;
#pragma unroll
        for (int o = 16; o > 0; o >>= 1) red += __shfl_down_sync(0xffffffffu, red, o);
        if (lane == 0) atomicAdd(&qsq[row], red);   // all lanes of a warp share one row
    }
    // W load: native row-major 256 x 128 fp32 -> bf16 (stride 272)
#pragma unroll 4
    for (int j = 0; j < 32; j++) {
        int i4 = t + j * 256;               // float4-chunk: 32 per W row
        int d = i4 >> 5, c4 = (i4 & 31) * 4;
        float4 w = *(const float4*)(W + d * DC + c4);
        uint2 pk;
        pk.x = pack_bf16(w.x, w.y);
        pk.y = pack_bf16(w.z, w.w);
        *(uint2*)(sm + QOFF_W + d * TSTRIDE + c4 * 2) = pk;
    }
    __syncthreads();

    if (t < 64) {
        float s = qsq[t];
        g_qinfo[q0 + t] = make_float2(s, 1.f - fminf(s, ONE_MEPS));
    }

    float acc[32];
#pragma unroll
    for (int i = 0; i < 32; i++) acc[i] = 0.f;
    const int m0 = (wid & 1) * 32, n0 = (wid >> 1) * 32;
    gemm_qw32(smem_u32(sm + QOFF_A), smem_u32(sm + QOFF_W), m0, n0, lane, acc);

    const int g = lane >> 2, qd = lane & 3;
#pragma unroll
    for (int n = 0; n < 4; n++) {
        int col = n0 + n * 8 + qd * 2;
#pragma unroll
        for (int mt = 0; mt < 2; mt++) {
#pragma unroll
            for (int h = 0; h < 2; h++) {
                int row = m0 + mt * 16 + h * 8 + g;
                int idx = n * 8 + mt * 4 + h * 2;
                *(uint32_t*)((char*)g_qp + (q0 + row) * 256 + col * 2) =
                    pack_bf16(acc[idx], acc[idx + 1]);
            }
        }
    }
}

// ==================== kernel 3: dequant k_c + k_sq = kc^T G kc (mma.sync) ====================
__global__ void __launch_bounds__(256) prep_k_kernel(const int* __restrict__ kq,
                                                     const float* __restrict__ ksc,
                                                     const float* __restrict__ kz) {
    extern __shared__ char sm[];
    const int t = threadIdx.x, wid = t >> 5, lane = t & 31;
    const int b = blockIdx.x >> 6;
    const int kt = blockIdx.x & 63;
    const size_t rowbase = (size_t)b * LK + (size_t)kt * 128;

    float* scs = (float*)(sm + OFF_INFO);
    float* zrs = (float*)(sm + OFF_INFO + 512);
    if (t < 128) {
        scs[t] = ksc[b * DC + t];
        zrs[t] = kz[b * DC + t];
    }
    __syncthreads();

#pragma unroll
    for (int i = 0; i < 8; i++) {
        int ci = t + i * 256;
        int row = ci >> 4, c16 = ci & 15;
        *(uint4*)(sm + OFF_B + row * TSTRIDE + c16 * 16) =
            *(const uint4*)((const char*)g_G + (size_t)row * 256 + (size_t)c16 * 16);
        const int4* src = (const int4*)(kq + (rowbase + row) * DC + c16 * 8);
        int4 v0 = src[0], v1 = src[1];
        int c0 = c16 * 8;
        float f0 = ((float)v0.x - zrs[c0 + 0]) * scs[c0 + 0];
        float f1 = ((float)v0.y - zrs[c0 + 1]) * scs[c0 + 1];
        float f2 = ((float)v0.z - zrs[c0 + 2]) * scs[c0 + 2];
        float f3 = ((float)v0.w - zrs[c0 + 3]) * scs[c0 + 3];
        float f4 = ((float)v1.x - zrs[c0 + 4]) * scs[c0 + 4];
        float f5 = ((float)v1.y - zrs[c0 + 5]) * scs[c0 + 5];
        float f6 = ((float)v1.z - zrs[c0 + 6]) * scs[c0 + 6];
        float f7 = ((float)v1.w - zrs[c0 + 7]) * scs[c0 + 7];
        uint4 pk;
        pk.x = pack_bf16(f0, f1); pk.y = pack_bf16(f2, f3);
        pk.z = pack_bf16(f4, f5); pk.w = pack_bf16(f6, f7);
        *(uint4*)(sm + OFF_A + row * TSTRIDE + c16 * 16) = pk;
        *(uint4*)((char*)g_kc + (rowbase + row) * 256 + (size_t)c16 * 16) = pk;
    }
    __syncthreads();

    float acc[64];
#pragma unroll
    for (int i = 0; i < 64; i++) acc[i] = 0.f;
    gemm128(smem_u32(sm + OFF_A), smem_u32(sm + OFF_B), wid, lane, acc);

    const int g = lane >> 2, qd = lane & 3;
    const int r0 = wid * 16 + g, r1 = r0 + 8;
    float p0 = 0.f, p1 = 0.f;
#pragma unroll
    for (int nt = 0; nt < 16; nt++) {
        int c0 = nt * 8 + qd * 2;
        __nv_bfloat162 kv0 = *(const __nv_bfloat162*)(sm + OFF_A + r0 * TSTRIDE + c0 * 2);
        __nv_bfloat162 kv1 = *(const __nv_bfloat162*)(sm + OFF_A + r1 * TSTRIDE + c0 * 2);
        float2 f0 = __bfloat1622float2(kv0), f1 = __bfloat1622float2(kv1);
        p0 = fmaf(acc[nt * 4 + 0], f0.x, fmaf(acc[nt * 4 + 1], f0.y, p0));
        p1 = fmaf(acc[nt * 4 + 2], f1.x, fmaf(acc[nt * 4 + 3], f1.y, p1));
    }
    p0 += __shfl_xor_sync(0xffffffffu, p0, 1);
    p0 += __shfl_xor_sync(0xffffffffu, p0, 2);
    p1 += __shfl_xor_sync(0xffffffffu, p1, 1);
    p1 += __shfl_xor_sync(0xffffffffu, p1, 2);
    if (qd == 0) {
        g_kinfo[rowbase + r0] = make_float2(p0, 1.f - fminf(p0, ONE_MEPS));
        g_kinfo[rowbase + r1] = make_float2(p1, 1.f - fminf(p1, ONE_MEPS));
    }
}

// ==================== kernel 4: main GEMM qk + hyperbolic-distance epilogue ====================
__global__ void __launch_bounds__(256) main_kernel(float* __restrict__ out) {
    extern __shared__ char sm[];
    const int t = threadIdx.x, wid = t >> 5, lane = t & 31;
    const int bx = blockIdx.x;
    const int b = bx >> 9;
    const int rem = bx & 511;
    const int kt = rem >> 3;     // 8 consecutive CTAs share the kc tile (L2 reuse)
    const int qt = rem & 7;
    const size_t q0 = (size_t)b * LQ + (size_t)qt * 128;
    const size_t k0 = (size_t)b * LK + (size_t)kt * 128;

#pragma unroll
    for (int i = 0; i < 8; i++) {
        int ci = t + i * 256;
        int row = ci >> 4, c16 = ci & 15;
        *(uint4*)(sm + OFF_A + row * TSTRIDE + c16 * 16) =
            *(const uint4*)((const char*)g_qp + (q0 + row) * 256 + (size_t)c16 * 16);
        *(uint4*)(sm + OFF_B + row * TSTRIDE + c16 * 16) =
            *(const uint4*)((const char*)g_kc + (k0 + row) * 256 + (size_t)c16 * 16);
    }
    int myflag = 1;
    if (t < 128) {
        float2 ki = g_kinfo[k0 + t];
        ((float2*)(sm + OFF_INFO))[t] = ki;
        myflag = (ki.y == AQ0);
    }
    const int ctaFastK = __syncthreads_and(myflag);

    float acc[64];
#pragma unroll
    for (int i = 0; i < 64; i++) acc[i] = 0.f;
    const int wm = wid & 3, wn = wid >> 2;
    const int m0 = wm * 32, n0 = wn * 64;
    gemm_wt(smem_u32(sm + OFF_A), smem_u32(sm + OFF_B), m0, n0, lane, acc);

    const int g = lane >> 2, qd = lane & 3;
    float2 qi[4];
#pragma unroll
    for (int mt = 0; mt < 2; mt++)
#pragma unroll
        for (int h = 0; h < 2; h++)
            qi[mt * 2 + h] = g_qinfo[q0 + m0 + mt * 16 + h * 8 + g];
    const bool fast = ctaFastK && (qi[0].y == AQ0) && (qi[1].y == AQ0) &&
                      (qi[2].y == AQ0) && (qi[3].y == AQ0);
    const float den0 = fmaf(AQ0, AQ0, FEPS);
    const float rden0 = __frcp_rn(den0);
    const float c4 = 4.f * rden0;
    const float2* kinf = (const float2*)(sm + OFF_INFO);
    const size_t obase = ((size_t)b * LQ + (size_t)qt * 128) * LK + (size_t)kt * 128;

#pragma unroll
    for (int np = 0; np < 4; np++) {
        int colA = n0 + np * 16 + qd * 2;   // group 2np
        int colB = colA + 8;                // group 2np+1
        float2 kiA0 = kinf[colA], kiA1 = kinf[colA + 1];
        float2 kiB0 = kinf[colB], kiB1 = kinf[colB + 1];
#pragma unroll
        for (int mt = 0; mt < 2; mt++) {
#pragma unroll
            for (int h = 0; h < 2; h++) {
                int row = m0 + mt * 16 + h * 8 + g;
                int idxA = (2 * np) * 8 + mt * 4 + h * 2;
                int idxB = idxA + 8;
                float2 qv = qi[mt * 2 + h];
                float2 u, v;
                if (fast) {
                    u.x = fast_dist(fmaxf(fmaf(acc[idxA], -2.f, qv.x + kiA0.x), 0.f), c4, rden0);
                    u.y = fast_dist(fmaxf(fmaf(acc[idxA + 1], -2.f, qv.x + kiA1.x), 0.f), c4, rden0);
                    v.x = fast_dist(fmaxf(fmaf(acc[idxB], -2.f, qv.x + kiB0.x), 0.f), c4, rden0);
                    v.y = fast_dist(fmaxf(fmaf(acc[idxB + 1], -2.f, qv.x + kiB1.x), 0.f), c4, rden0);
                } else {
                    u.x = hdist(acc[idxA], qv.x, qv.y, kiA0);
                    u.y = hdist(acc[idxA + 1], qv.x, qv.y, kiA1);
                    v.x = hdist(acc[idxB], qv.x, qv.y, kiB0);
                    v.y = hdist(acc[idxB + 1], qv.x, qv.y, kiB1);
                }
                // 4-lane repack: lane qd ends with 4 consecutive cols (16B) of this row.
                float2 tmp;
                tmp.x = (qd < 2) ? v.x : u.x;
                tmp.y = (qd < 2) ? v.y : u.y;
                tmp.x = __shfl_xor_sync(0xffffffffu, tmp.x, 2);
                tmp.y = __shfl_xor_sync(0xffffffffu, tmp.y, 2);
                float2 first, second;
                first.x = (qd < 2) ? u.x : tmp.x;  first.y = (qd < 2) ? u.y : tmp.y;
                second.x = (qd < 2) ? tmp.x : v.x; second.y = (qd < 2) ? tmp.y : v.y;
                float2 t2;
                t2.x = (qd & 1) ? first.x : second.x;
                t2.y = (qd & 1) ? first.y : second.y;
                t2.x = __shfl_xor_sync(0xffffffffu, t2.x, 1);
                t2.y = __shfl_xor_sync(0xffffffffu, t2.y, 1);
                if (qd & 1) { first = t2; } else { second = t2; }
                float4 o = make_float4(first.x, first.y, second.x, second.y);
                *(float4*)(out + obase + (size_t)row * LK + (n0 + np * 16 + qd * 4)) = o;
            }
        }
    }
}

// ==================== launch ====================
extern "C" void kernel_launch(void* const* d_in, const int* in_sizes, int n_in,
                              void* d_out, int out_size) {
    const float* q   = (const float*)d_in[0];
    const int*   kq  = (const int*)d_in[1];
    const float* ksc = (const float*)d_in[2];
    const float* kz  = (const float*)d_in[3];
    const float* W   = (const float*)d_in[4];
    float* out = (float*)d_out;

    cudaFuncSetAttribute(prep_q_kernel, cudaFuncAttributeMaxDynamicSharedMemorySize, SMEM_Q);
    cudaFuncSetAttribute(prep_k_kernel, cudaFuncAttributeMaxDynamicSharedMemorySize, SMEM_DYN);
    cudaFuncSetAttribute(main_kernel, cudaFuncAttributeMaxDynamicSharedMemorySize, SMEM_DYN);

    prep_G_kernel<<<64, 256>>>(W);
    prep_q_kernel<<<NB * LQ / 64, 256, SMEM_Q>>>(q, W);
    prep_k_kernel<<<NB * (LK / 128), 256, SMEM_DYN>>>(kq, ksc, kz);
    main_kernel<<<NB * (LQ / 128) * (LK / 128), 256, SMEM_DYN>>>(out);
}

// round 14
// speedup vs baseline: 1.0160x; 1.0160x over previous
#include <cuda_runtime.h>
#include <cuda_bf16.h>
#include <cstdint>

#define NB 8
#define LQ 1024
#define LK 8192
#define DIMD 256
#define DC 128
#define FEPS 1e-6f
#define ONE_MEPS (1.0f - 1e-6f)
#define AQ0 (1.0f - ONE_MEPS)

// -------------------- device scratch (no allocs allowed) --------------------
__device__ __nv_bfloat16 g_G[DC * DC];                 // W^T W, bf16, row-major
__device__ __nv_bfloat16 g_qp[NB * LQ * DC];           // q' = q @ W_up, bf16
__device__ float2 g_qinfo[NB * LQ];                    // (q_sq, 1-min(q_sq,1-eps))
__device__ __nv_bfloat16 g_kc[(size_t)NB * LK * DC];   // dequantized k_c, bf16
__device__ float2 g_kinfo[NB * LK];                    // (k_sq, 1-min(k_sq,1-eps))

// -------------------- helpers --------------------
static __device__ __forceinline__ uint32_t smem_u32(const void* p) {
    uint32_t a;
    asm("{ .reg .u64 t; cvta.to.shared.u64 t, %1; cvt.u32.u64 %0, t; }" : "=r"(a) : "l"(p));
    return a;
}

#define LDSM4(r0, r1, r2, r3, a) \
    asm volatile("ldmatrix.sync.aligned.m8n8.x4.shared.b16 {%0,%1,%2,%3}, [%4];" \
                 : "=r"(r0), "=r"(r1), "=r"(r2), "=r"(r3) : "r"(a))

#define LDSM4T(r0, r1, r2, r3, a) \
    asm volatile("ldmatrix.sync.aligned.m8n8.x4.trans.shared.b16 {%0,%1,%2,%3}, [%4];" \
                 : "=r"(r0), "=r"(r1), "=r"(r2), "=r"(r3) : "r"(a))

#define MMA16816(c, a0, a1, a2, a3, b0, b1) \
    asm volatile("mma.sync.aligned.m16n8k16.row.col.f32.bf16.bf16.f32 " \
                 "{%0,%1,%2,%3},{%4,%5,%6,%7},{%8,%9},{%0,%1,%2,%3};" \
                 : "+f"((c)[0]), "+f"((c)[1]), "+f"((c)[2]), "+f"((c)[3]) \
                 : "r"(a0), "r"(a1), "r"(a2), "r"(a3), "r"(b0), "r"(b1))

static __device__ __forceinline__ uint32_t pack_bf16(float a, float b) {
    __nv_bfloat162 h = __floats2bfloat162_rn(a, b);
    return *reinterpret_cast<uint32_t*>(&h);
}

// -------------------- SMEM layouts --------------------
#define TSTRIDE 272
#define OFF_A 0                       // 34816 B
#define OFF_B 34816                   // 34816 B
#define OFF_INFO 69632                // 1024 B
#define SMEM_DYN 70656
// prep_q: A = q tile 64 rows x 256 bf16, stride 528B; W native 256 rows x 128 bf16, stride 272B.
#define QSTRIDE 528
#define QOFF_A 0                      // 64*528 = 33792
#define QOFF_W 33792                  // 256*272 = 69632 -> ends 103424
#define QOFF_SQ 103424                // float[64]
#define SMEM_Q 103936

// ---- warp-tile GEMM: 32(M) x 64(N) per warp, K = 128, both operands k-major ----
static __device__ __forceinline__ void gemm_wt(uint32_t aBase, uint32_t bBase,
                                               int m0, int n0, int lane, float* acc) {
    uint32_t aAddr0 = aBase + (uint32_t)(m0 + (lane & 15)) * TSTRIDE + (uint32_t)((lane >> 4) << 4);
    uint32_t aAddr1 = aAddr0 + 16 * TSTRIDE;
    uint32_t bAddr = bBase + (uint32_t)(n0 + (lane & 7) + ((lane >> 4) << 3)) * TSTRIDE +
                     (uint32_t)(((lane >> 3) & 1) << 4);
#pragma unroll
    for (int kk = 0; kk < 8; kk++) {
        uint32_t a0, a1, a2, a3, c0, c1, c2, c3;
        LDSM4(a0, a1, a2, a3, aAddr0 + kk * 32);
        LDSM4(c0, c1, c2, c3, aAddr1 + kk * 32);
#pragma unroll
        for (int j = 0; j < 4; j++) {
            uint32_t b0, b1, b2, b3;
            LDSM4(b0, b1, b2, b3, bAddr + j * (16 * TSTRIDE) + kk * 32);
            MMA16816(acc + (2 * j) * 8 + 0, a0, a1, a2, a3, b0, b1);
            MMA16816(acc + (2 * j) * 8 + 4, c0, c1, c2, c3, b0, b1);
            MMA16816(acc + (2 * j + 1) * 8 + 0, a0, a1, a2, a3, b2, b3);
            MMA16816(acc + (2 * j + 1) * 8 + 4, c0, c1, c2, c3, b2, b3);
        }
    }
}

// ---- prep_q GEMM: warp tile 32(M) x 32(N), K=256; B = W native row-major via ldmatrix.trans ----
static __device__ __forceinline__ void gemm_qw32(uint32_t aBase, uint32_t wBase,
                                                 int m0, int n0, int lane, float* acc) {
    uint32_t aAddr0 = aBase + (uint32_t)(m0 + (lane & 15)) * QSTRIDE + (uint32_t)((lane >> 4) << 4);
    uint32_t aAddr1 = aAddr0 + 16 * QSTRIDE;
    uint32_t bAddr = wBase + (uint32_t)(lane & 15) * TSTRIDE + (uint32_t)((lane >> 4) << 4) +
                     (uint32_t)(n0 * 2);
#pragma unroll
    for (int kk = 0; kk < 16; kk++) {
        uint32_t a0, a1, a2, a3, c0, c1, c2, c3;
        LDSM4(a0, a1, a2, a3, aAddr0 + kk * 32);
        LDSM4(c0, c1, c2, c3, aAddr1 + kk * 32);
        uint32_t brow = bAddr + (uint32_t)(kk * 16) * TSTRIDE;
#pragma unroll
        for (int j = 0; j < 2; j++) {
            uint32_t b0, b1, b2, b3;
            LDSM4T(b0, b1, b2, b3, brow + j * 32);
            MMA16816(acc + (2 * j) * 8 + 0, a0, a1, a2, a3, b0, b1);
            MMA16816(acc + (2 * j) * 8 + 4, c0, c1, c2, c3, b0, b1);
            MMA16816(acc + (2 * j + 1) * 8 + 0, a0, a1, a2, a3, b2, b3);
            MMA16816(acc + (2 * j + 1) * 8 + 4, c0, c1, c2, c3, b2, b3);
        }
    }
}

// ---- legacy 8x1 warp tiling (kept for prep_k) ----
static __device__ __forceinline__ void gemm128(uint32_t aBase, uint32_t bBase,
                                               int wid, int lane, float* acc) {
    uint32_t aAddr = aBase + (uint32_t)(wid * 16 + (lane & 15)) * TSTRIDE +
                     (uint32_t)((lane >> 4) << 4);
    uint32_t bAddr = bBase + (uint32_t)((lane & 7) + ((lane >> 4) << 3)) * TSTRIDE +
                     (uint32_t)(((lane >> 3) & 1) << 4);
#pragma unroll
    for (int kk = 0; kk < 8; kk++) {
        uint32_t a0, a1, a2, a3;
        LDSM4(a0, a1, a2, a3, aAddr + kk * 32);
#pragma unroll
        for (int nt2 = 0; nt2 < 8; nt2++) {
            uint32_t b0, b1, b2, b3;
            LDSM4(b0, b1, b2, b3, bAddr + nt2 * (16 * TSTRIDE) + kk * 32);
            MMA16816(acc + nt2 * 8, a0, a1, a2, a3, b0, b1);
            MMA16816(acc + nt2 * 8 + 4, a0, a1, a2, a3, b2, b3);
        }
    }
}

// general path (rare): full clamp math incl. per-pair division
static __device__ __forceinline__ float hdist(float qk, float qs, float aq, float2 ki) {
    float diff = fmaxf(fmaf(qk, -2.f, qs + ki.x), 0.f);
    float den = fmaf(aq, ki.y, FEPS);
    float x = __fdividef(diff + diff, den) + 1.f;
    float arg;
    if (x > 100.f) arg = x + x;
    else arg = x + sqrtf(fmaxf(fmaf(x, x, -1.f), 0.f));
    return __logf(arg);
}

// fast path: den == den0 constant; dist = ln(4*diff/den0), exact fallback for small diff
static __device__ __forceinline__ float fast_dist(float diff, float c4, float rden0) {
    float v = diff * c4;                      // 4*diff/den0
    if (v > 1e4f) return __logf(v);
    float x = fmaf(diff + diff, rden0, 1.f);  // 1 + 2*diff/den0
    return __logf(x + sqrtf(fmaxf(fmaf(x, x, -1.f), 0.f)));
}

// ==================== kernel 1: G = W^T W (bf16) ====================
__global__ void prep_G_kernel(const float* __restrict__ W) {
    int idx = blockIdx.x * 256 + threadIdx.x;  // 16384 entries
    int c = idx >> 7, c2 = idx & 127;
    float s = 0.f;
#pragma unroll 4
    for (int d = 0; d < DIMD; d++) s = fmaf(W[d * DC + c], W[d * DC + c2], s);
    g_G[idx] = __float2bfloat16(s);
}

// ==================== kernel 2: q' = q @ W_up (tensor), q_sq (fp32 exact) ====================
__global__ void __launch_bounds__(256) prep_q_kernel(const float* __restrict__ q,
                                                     const float* __restrict__ W) {
    extern __shared__ char sm[];
    const int t = threadIdx.x, wid = t >> 5, lane = t & 31;
    const size_t q0 = (size_t)blockIdx.x * 64;
    float* qsq = (float*)(sm + QOFF_SQ);

    if (t < 64) qsq[t] = 0.f;
    __syncthreads();

    // A load: q tile 64 x 256 fp32 -> bf16 (stride 528), accumulate q_sq (fp32 exact).
#pragma unroll 4
    for (int j = 0; j < 16; j++) {
        int ci = t + j * 256;               // float4-chunk index: 64 per row
        int row = ci >> 6, c4 = ci & 63;
        float4 v = *(const float4*)(q + (q0 + row) * DIMD + c4 * 4);
        uint2 pk;
        pk.x = pack_bf16(v.x, v.y);
        pk.y = pack_bf16(v.z, v.w);
        *(uint2*)(sm + QOFF_A + row * QSTRIDE + c4 * 8) = pk;
        float red = v.x * v.x + v.y * v.y + v.z * v.z + v.w * v.w;
#pragma unroll
        for (int o = 16; o > 0; o >>= 1) red += __shfl_down_sync(0xffffffffu, red, o);
        if (lane == 0) atomicAdd(&qsq[row], red);   // all lanes of a warp share one row
    }
    // W load: native row-major 256 x 128 fp32 -> bf16 (stride 272)
#pragma unroll 4
    for (int j = 0; j < 32; j++) {
        int i4 = t + j * 256;               // float4-chunk: 32 per W row
        int d = i4 >> 5, c4 = (i4 & 31) * 4;
        float4 w = *(const float4*)(W + d * DC + c4);
        uint2 pk;
        pk.x = pack_bf16(w.x, w.y);
        pk.y = pack_bf16(w.z, w.w);
        *(uint2*)(sm + QOFF_W + d * TSTRIDE + c4 * 2) = pk;
    }
    __syncthreads();

    if (t < 64) {
        float s = qsq[t];
        g_qinfo[q0 + t] = make_float2(s, 1.f - fminf(s, ONE_MEPS));
    }

    float acc[32];
#pragma unroll
    for (int i = 0; i < 32; i++) acc[i] = 0.f;
    const int m0 = (wid & 1) * 32, n0 = (wid >> 1) * 32;
    gemm_qw32(smem_u32(sm + QOFF_A), smem_u32(sm + QOFF_W), m0, n0, lane, acc);

    const int g = lane >> 2, qd = lane & 3;
#pragma unroll
    for (int n = 0; n < 4; n++) {
        int col = n0 + n * 8 + qd * 2;
#pragma unroll
        for (int mt = 0; mt < 2; mt++) {
#pragma unroll
            for (int h = 0; h < 2; h++) {
                int row = m0 + mt * 16 + h * 8 + g;
                int idx = n * 8 + mt * 4 + h * 2;
                *(uint32_t*)((char*)g_qp + (q0 + row) * 256 + col * 2) =
                    pack_bf16(acc[idx], acc[idx + 1]);
            }
        }
    }
}

// ==================== kernel 3: dequant k_c + k_sq = kc^T G kc (mma.sync) ====================
__global__ void __launch_bounds__(256) prep_k_kernel(const int* __restrict__ kq,
                                                     const float* __restrict__ ksc,
                                                     const float* __restrict__ kz) {
    extern __shared__ char sm[];
    const int t = threadIdx.x, wid = t >> 5, lane = t & 31;
    const int b = blockIdx.x >> 6;
    const int kt = blockIdx.x & 63;
    const size_t rowbase = (size_t)b * LK + (size_t)kt * 128;

    float* scs = (float*)(sm + OFF_INFO);
    float* zrs = (float*)(sm + OFF_INFO + 512);
    if (t < 128) {
        scs[t] = ksc[b * DC + t];
        zrs[t] = kz[b * DC + t];
    }
    __syncthreads();

#pragma unroll
    for (int i = 0; i < 8; i++) {
        int ci = t + i * 256;
        int row = ci >> 4, c16 = ci & 15;
        *(uint4*)(sm + OFF_B + row * TSTRIDE + c16 * 16) =
            *(const uint4*)((const char*)g_G + (size_t)row * 256 + (size_t)c16 * 16);
        const int4* src = (const int4*)(kq + (rowbase + row) * DC + c16 * 8);
        int4 v0 = src[0], v1 = src[1];
        int c0 = c16 * 8;
        float f0 = ((float)v0.x - zrs[c0 + 0]) * scs[c0 + 0];
        float f1 = ((float)v0.y - zrs[c0 + 1]) * scs[c0 + 1];
        float f2 = ((float)v0.z - zrs[c0 + 2]) * scs[c0 + 2];
        float f3 = ((float)v0.w - zrs[c0 + 3]) * scs[c0 + 3];
        float f4 = ((float)v1.x - zrs[c0 + 4]) * scs[c0 + 4];
        float f5 = ((float)v1.y - zrs[c0 + 5]) * scs[c0 + 5];
        float f6 = ((float)v1.z - zrs[c0 + 6]) * scs[c0 + 6];
        float f7 = ((float)v1.w - zrs[c0 + 7]) * scs[c0 + 7];
        uint4 pk;
        pk.x = pack_bf16(f0, f1); pk.y = pack_bf16(f2, f3);
        pk.z = pack_bf16(f4, f5); pk.w = pack_bf16(f6, f7);
        *(uint4*)(sm + OFF_A + row * TSTRIDE + c16 * 16) = pk;
        *(uint4*)((char*)g_kc + (rowbase + row) * 256 + (size_t)c16 * 16) = pk;
    }
    __syncthreads();

    float acc[64];
#pragma unroll
    for (int i = 0; i < 64; i++) acc[i] = 0.f;
    gemm128(smem_u32(sm + OFF_A), smem_u32(sm + OFF_B), wid, lane, acc);

    const int g = lane >> 2, qd = lane & 3;
    const int r0 = wid * 16 + g, r1 = r0 + 8;
    float p0 = 0.f, p1 = 0.f;
#pragma unroll
    for (int nt = 0; nt < 16; nt++) {
        int c0 = nt * 8 + qd * 2;
        __nv_bfloat162 kv0 = *(const __nv_bfloat162*)(sm + OFF_A + r0 * TSTRIDE + c0 * 2);
        __nv_bfloat162 kv1 = *(const __nv_bfloat162*)(sm + OFF_A + r1 * TSTRIDE + c0 * 2);
        float2 f0 = __bfloat1622float2(kv0), f1 = __bfloat1622float2(kv1);
        p0 = fmaf(acc[nt * 4 + 0], f0.x, fmaf(acc[nt * 4 + 1], f0.y, p0));
        p1 = fmaf(acc[nt * 4 + 2], f1.x, fmaf(acc[nt * 4 + 3], f1.y, p1));
    }
    p0 += __shfl_xor_sync(0xffffffffu, p0, 1);
    p0 += __shfl_xor_sync(0xffffffffu, p0, 2);
    p1 += __shfl_xor_sync(0xffffffffu, p1, 1);
    p1 += __shfl_xor_sync(0xffffffffu, p1, 2);
    if (qd == 0) {
        g_kinfo[rowbase + r0] = make_float2(p0, 1.f - fminf(p0, ONE_MEPS));
        g_kinfo[rowbase + r1] = make_float2(p1, 1.f - fminf(p1, ONE_MEPS));
    }
}

// ==================== kernel 4: main GEMM qk + hyperbolic-distance epilogue ====================
__global__ void __launch_bounds__(256) main_kernel(float* __restrict__ out) {
    extern __shared__ char sm[];
    const int t = threadIdx.x, wid = t >> 5, lane = t & 31;
    const int bx = blockIdx.x;
    const int b = bx >> 9;
    const int rem = bx & 511;
    const int kt = rem >> 3;     // 8 consecutive CTAs share the kc tile (L2 reuse)
    const int qt = rem & 7;
    const size_t q0 = (size_t)b * LQ + (size_t)qt * 128;
    const size_t k0 = (size_t)b * LK + (size_t)kt * 128;

#pragma unroll
    for (int i = 0; i < 8; i++) {
        int ci = t + i * 256;
        int row = ci >> 4, c16 = ci & 15;
        *(uint4*)(sm + OFF_A + row * TSTRIDE + c16 * 16) =
            *(const uint4*)((const char*)g_qp + (q0 + row) * 256 + (size_t)c16 * 16);
        *(uint4*)(sm + OFF_B + row * TSTRIDE + c16 * 16) =
            *(const uint4*)((const char*)g_kc + (k0 + row) * 256 + (size_t)c16 * 16);
    }
    int myflag = 1;
    if (t < 128) {
        float2 ki = g_kinfo[k0 + t];
        ((float2*)(sm + OFF_INFO))[t] = ki;
        myflag = (ki.y == AQ0);
    }
    const int ctaFastK = __syncthreads_and(myflag);

    float acc[64];
#pragma unroll
    for (int i = 0; i < 64; i++) acc[i] = 0.f;
    const int wm = wid & 3, wn = wid >> 2;
    const int m0 = wm * 32, n0 = wn * 64;
    gemm_wt(smem_u32(sm + OFF_A), smem_u32(sm + OFF_B), m0, n0, lane, acc);

    const int g = lane >> 2, qd = lane & 3;
    float2 qi[4];
#pragma unroll
    for (int mt = 0; mt < 2; mt++)
#pragma unroll
        for (int h = 0; h < 2; h++)
            qi[mt * 2 + h] = g_qinfo[q0 + m0 + mt * 16 + h * 8 + g];
    const bool fast = ctaFastK && (qi[0].y == AQ0) && (qi[1].y == AQ0) &&
                      (qi[2].y == AQ0) && (qi[3].y == AQ0);
    const float den0 = fmaf(AQ0, AQ0, FEPS);
    const float rden0 = __frcp_rn(den0);
    const float c4 = 4.f * rden0;
    const float2* kinf = (const float2*)(sm + OFF_INFO);
    const size_t obase = ((size_t)b * LQ + (size_t)qt * 128) * LK + (size_t)kt * 128;

#pragma unroll
    for (int n = 0; n < 8; n++) {
        int col = n0 + n * 8 + qd * 2;
        float2 ki0 = kinf[col], ki1 = kinf[col + 1];
#pragma unroll
        for (int mt = 0; mt < 2; mt++) {
#pragma unroll
            for (int h = 0; h < 2; h++) {
                int row = m0 + mt * 16 + h * 8 + g;
                int idx = n * 8 + mt * 4 + h * 2;
                float2 qv = qi[mt * 2 + h];
                float d0, d1;
                if (fast) {
                    d0 = fast_dist(fmaxf(fmaf(acc[idx], -2.f, qv.x + ki0.x), 0.f), c4, rden0);
                    d1 = fast_dist(fmaxf(fmaf(acc[idx + 1], -2.f, qv.x + ki1.x), 0.f), c4, rden0);
                } else {
                    d0 = hdist(acc[idx], qv.x, qv.y, ki0);
                    d1 = hdist(acc[idx + 1], qv.x, qv.y, ki1);
                }
                *(float2*)(out + obase + (size_t)row * LK + col) = make_float2(d0, d1);
            }
        }
    }
}

// ==================== launch ====================
extern "C" void kernel_launch(void* const* d_in, const int* in_sizes, int n_in,
                              void* d_out, int out_size) {
    const float* q   = (const float*)d_in[0];
    const int*   kq  = (const int*)d_in[1];
    const float* ksc = (const float*)d_in[2];
    const float* kz  = (const float*)d_in[3];
    const float* W   = (const float*)d_in[4];
    float* out = (float*)d_out;

    cudaFuncSetAttribute(prep_q_kernel, cudaFuncAttributeMaxDynamicSharedMemorySize, SMEM_Q);
    cudaFuncSetAttribute(prep_k_kernel, cudaFuncAttributeMaxDynamicSharedMemorySize, SMEM_DYN);
    cudaFuncSetAttribute(main_kernel, cudaFuncAttributeMaxDynamicSharedMemorySize, SMEM_DYN);

    prep_G_kernel<<<64, 256>>>(W);
    prep_q_kernel<<<NB * LQ / 64, 256, SMEM_Q>>>(q, W);
    prep_k_kernel<<<NB * (LK / 128), 256, SMEM_DYN>>>(kq, ksc, kz);
    main_kernel<<<NB * (LQ / 128) * (LK / 128), 256, SMEM_DYN>>>(out);
}